// round 5
// baseline (speedup 1.0000x reference)
#include <cuda_runtime.h>
#include <cuda_bf16.h>
#include <cstdint>
#include <cstddef>

#define B_DIM 8192
#define HIN   4096
#define HOUT  4096
#define KE    4128          // 4096 + 32 LoRA cols = 129 chunks of K=32

// ---------------- device scratch ----------------
__device__ __align__(16) float g_aw[B_DIM * 32];
__device__ __align__(16) __nv_bfloat16 g_xh[(size_t)B_DIM * KE];
__device__ __align__(16) __nv_bfloat16 g_xl[(size_t)B_DIM * KE];
__device__ __align__(16) __nv_bfloat16 g_wh[(size_t)HOUT * KE];
__device__ __align__(16) __nv_bfloat16 g_wl[(size_t)HOUT * KE];

// ---------------- helpers ----------------
__device__ __forceinline__ uint32_t smem_u32(const void* p) {
    uint32_t a;
    asm("{ .reg .u64 t; cvta.to.shared.u64 t, %1; cvt.u32.u64 %0, t; }" : "=r"(a) : "l"(p));
    return a;
}

__device__ __forceinline__ void split4(float4 f, uint2& hv, uint2& lv) {
    __nv_bfloat16 h0 = __float2bfloat16(f.x);
    __nv_bfloat16 h1 = __float2bfloat16(f.y);
    __nv_bfloat16 h2 = __float2bfloat16(f.z);
    __nv_bfloat16 h3 = __float2bfloat16(f.w);
    __nv_bfloat16 l0 = __float2bfloat16(f.x - __bfloat162float(h0));
    __nv_bfloat16 l1 = __float2bfloat16(f.y - __bfloat162float(h1));
    __nv_bfloat16 l2 = __float2bfloat16(f.z - __bfloat162float(h2));
    __nv_bfloat16 l3 = __float2bfloat16(f.w - __bfloat162float(h3));
    hv.x = (uint32_t)__bfloat16_as_ushort(h0) | ((uint32_t)__bfloat16_as_ushort(h1) << 16);
    hv.y = (uint32_t)__bfloat16_as_ushort(h2) | ((uint32_t)__bfloat16_as_ushort(h3) << 16);
    lv.x = (uint32_t)__bfloat16_as_ushort(l0) | ((uint32_t)__bfloat16_as_ushort(l1) << 16);
    lv.y = (uint32_t)__bfloat16_as_ushort(l2) | ((uint32_t)__bfloat16_as_ushort(l3) << 16);
}

__device__ __forceinline__ void cpa16(uint32_t dst, const void* src) {
    asm volatile("cp.async.cg.shared.global [%0], [%1], 16;" :: "r"(dst), "l"(src));
}

__device__ __forceinline__ void ldm4(uint32_t* r, uint32_t addr) {
    asm volatile("ldmatrix.sync.aligned.m8n8.x4.shared.b16 {%0,%1,%2,%3}, [%4];"
                 : "=r"(r[0]), "=r"(r[1]), "=r"(r[2]), "=r"(r[3]) : "r"(addr));
}

__device__ __forceinline__ void mma16816(float* c, const uint32_t* a, uint32_t b0, uint32_t b1) {
    asm volatile(
        "mma.sync.aligned.m16n8k16.row.col.f32.bf16.bf16.f32 "
        "{%0,%1,%2,%3}, {%4,%5,%6,%7}, {%8,%9}, {%0,%1,%2,%3};"
        : "+f"(c[0]), "+f"(c[1]), "+f"(c[2]), "+f"(c[3])
        : "r"(a[0]), "r"(a[1]), "r"(a[2]), "r"(a[3]), "r"(b0), "r"(b1));
}

// ================= Stage 1: aw = (x @ qa^T) * tkw =================
__global__ void __launch_bounds__(256) lora_a_kernel(
    const float* __restrict__ x, const float* __restrict__ tkw, const float* __restrict__ qa)
{
    __shared__ float xs[64][64];
    __shared__ float qs[64][33];
    const int tid  = threadIdx.x;
    const int lane = tid & 31, w = tid >> 5;
    const int b0   = blockIdx.x * 64;

    float acc[8] = {0.f, 0.f, 0.f, 0.f, 0.f, 0.f, 0.f, 0.f};

    for (int k0 = 0; k0 < HIN; k0 += 64) {
        __syncthreads();
        #pragma unroll
        for (int i = 0; i < 4; i++) {
            int v = tid + i * 256;
            int r = v >> 4, c = (v & 15) << 2;
            *reinterpret_cast<float4*>(&xs[r][c]) =
                *reinterpret_cast<const float4*>(x + (size_t)(b0 + r) * HIN + k0 + c);
        }
        #pragma unroll
        for (int i = 0; i < 2; i++) {
            int v = tid + i * 256;
            int kr = v >> 4, c = (v & 15) << 2;
            float4 f = *reinterpret_cast<const float4*>(qa + (size_t)kr * HIN + k0 + c);
            qs[c + 0][kr] = f.x; qs[c + 1][kr] = f.y;
            qs[c + 2][kr] = f.z; qs[c + 3][kr] = f.w;
        }
        __syncthreads();
        #pragma unroll
        for (int kk = 0; kk < 64; kk += 4) {
            float q0 = qs[kk][lane], q1 = qs[kk + 1][lane];
            float q2 = qs[kk + 2][lane], q3 = qs[kk + 3][lane];
            #pragma unroll
            for (int i = 0; i < 8; i++) {
                float4 xv = *reinterpret_cast<const float4*>(&xs[w * 8 + i][kk]);
                acc[i] += xv.x * q0 + xv.y * q1 + xv.z * q2 + xv.w * q3;
            }
        }
    }
    #pragma unroll
    for (int i = 0; i < 8; i++) {
        int b = b0 + w * 8 + i;
        g_aw[b * 32 + lane] = acc[i] * tkw[b * 4 + (lane >> 3)];
    }
}

// ================= Stage 2a: convert x (+aw) to bf16 hi/lo planes =================
__global__ void __launch_bounds__(256) cvt_x_kernel(const float* __restrict__ x)
{
    const int b = blockIdx.x, tid = threadIdx.x;
    const size_t rb = (size_t)b * KE;
    uint2 hv, lv;
    #pragma unroll
    for (int i = 0; i < 4; i++) {
        int c4 = (tid + i * 256) << 2;
        float4 f = *reinterpret_cast<const float4*>(x + (size_t)b * HIN + c4);
        split4(f, hv, lv);
        *reinterpret_cast<uint2*>(g_xh + rb + c4) = hv;
        *reinterpret_cast<uint2*>(g_xl + rb + c4) = lv;
    }
    if (tid < 8) {
        int c4 = 4096 + tid * 4;
        float4 f = *reinterpret_cast<const float4*>(g_aw + b * 32 + tid * 4);
        split4(f, hv, lv);
        *reinterpret_cast<uint2*>(g_xh + rb + c4) = hv;
        *reinterpret_cast<uint2*>(g_xl + rb + c4) = lv;
    }
}

// ================= Stage 2b: convert W (+scaling*qb) to bf16 hi/lo planes =========
__global__ void __launch_bounds__(256) cvt_w_kernel(
    const float* __restrict__ W, const float* __restrict__ qb, const float* __restrict__ scaling)
{
    const int o = blockIdx.x, tid = threadIdx.x;
    const size_t rb = (size_t)o * KE;
    uint2 hv, lv;
    #pragma unroll
    for (int i = 0; i < 4; i++) {
        int c4 = (tid + i * 256) << 2;
        float4 f = *reinterpret_cast<const float4*>(W + (size_t)o * HIN + c4);
        split4(f, hv, lv);
        *reinterpret_cast<uint2*>(g_wh + rb + c4) = hv;
        *reinterpret_cast<uint2*>(g_wl + rb + c4) = lv;
    }
    if (tid < 8) {
        int c4 = 4096 + tid * 4;
        int kk = tid >> 1, rr = (tid & 1) * 4;       // kr = kk*8 + rr..rr+3
        const float* p = qb + ((size_t)kk * HOUT + o) * 8 + rr;
        float sc = scaling[o];
        float4 f = make_float4(p[0] * sc, p[1] * sc, p[2] * sc, p[3] * sc);
        split4(f, hv, lv);
        *reinterpret_cast<uint2*>(g_wh + rb + c4) = hv;
        *reinterpret_cast<uint2*>(g_wl + rb + c4) = lv;
    }
}

// ================= Stage 3: GEMM =================
// 2 CTAs/SM, 256 threads (8 warps, 4x2), CTA tile M=128 x N=128, K=32 chunks.
// Smem row = 128B: [hi 64B | lo 64B] per logical row; 3-stage cp.async pipeline.
#define A_OFF   0
#define W_OFF   16384
#define STAGE_B 32768
#define NSTAGE  3
#define SMEM_TOTAL (NSTAGE * STAGE_B)
#define NCHUNK  129

__device__ __forceinline__ void issue_stage(uint32_t st, int ch, int m0, int n0, int tid)
{
    const int r = tid >> 1, h = tid & 1;             // row 0..127, plane hi/lo
    const __nv_bfloat16* xp = h ? g_xl : g_xh;
    const __nv_bfloat16* wp = h ? g_wl : g_wh;
    const size_t kofs = (size_t)ch * 32;
    const uint32_t rb = (uint32_t)r * 128u;
    const uint32_t hb = (uint32_t)h * 64u;
    const uint32_t rx = ((uint32_t)(r & 7) << 4);
    const size_t ga = (size_t)(m0 + r) * KE + kofs;
    const size_t gw = (size_t)(n0 + r) * KE + kofs;
    #pragma unroll
    for (int s = 0; s < 4; s++) {
        uint32_t d = rb + ((hb + s * 16u) ^ rx);
        cpa16(st + A_OFF + d, xp + ga + s * 8);
        cpa16(st + W_OFF + d, wp + gw + s * 8);
    }
    asm volatile("cp.async.commit_group;" ::: "memory");
}

__global__ void __launch_bounds__(256, 2) fused_gemm_kernel(float* __restrict__ out)
{
    extern __shared__ char smem[];
    const int tid = threadIdx.x;
    const int wid = tid >> 5, lid = tid & 31;
    const int wr = wid >> 1, wc = wid & 1;           // 4x2 warp grid: M 32-rows, N 64-cols
    const int n0 = blockIdx.x * 128;
    const int m0 = blockIdx.y * 128;
    const uint32_t sbase = smem_u32(smem);
    const int lr = lid & 15;
    const uint32_t lhb = (uint32_t)(lid >> 4) * 16u;

    float acc[2][8][4];
    #pragma unroll
    for (int t = 0; t < 2; t++)
        #pragma unroll
        for (int j = 0; j < 8; j++)
            #pragma unroll
            for (int e = 0; e < 4; e++) acc[t][j][e] = 0.f;

    issue_stage(sbase, 0, m0, n0, tid);
    issue_stage(sbase + STAGE_B, 1, m0, n0, tid);

    int sidx = 0;
    for (int ch = 0; ch < NCHUNK; ch++) {
        const uint32_t st = sbase + sidx * STAGE_B;

        asm volatile("cp.async.wait_group 1;" ::: "memory");
        __syncthreads();
        if (ch + 2 < NCHUNK) {
            int ps = sidx + 2; if (ps >= NSTAGE) ps -= NSTAGE;
            issue_stage(sbase + ps * STAGE_B, ch + 2, m0, n0, tid);
        }

        #pragma unroll
        for (int ks = 0; ks < 2; ks++) {
            const uint32_t chb = (uint32_t)ks * 32u + lhb;   // hi cols byte offset
            uint32_t ah[2][4], al[2][4];
            #pragma unroll
            for (int t = 0; t < 2; t++) {
                uint32_t row = (uint32_t)(wr * 32 + t * 16 + lr);
                uint32_t rb = row * 128u, rx = (row & 7u) << 4;
                ldm4(ah[t], st + A_OFF + rb + (chb ^ rx));
                ldm4(al[t], st + A_OFF + rb + ((chb + 64u) ^ rx));
            }
            #pragma unroll
            for (int g = 0; g < 4; g++) {
                uint32_t row = (uint32_t)(wc * 64 + g * 16 + lr);
                uint32_t rb = row * 128u, rx = (row & 7u) << 4;
                uint32_t bh[4], bl[4];
                ldm4(bh, st + W_OFF + rb + (chb ^ rx));
                ldm4(bl, st + W_OFF + rb + ((chb + 64u) ^ rx));
                #pragma unroll
                for (int t = 0; t < 2; t++) {
                    #pragma unroll
                    for (int j2 = 0; j2 < 2; j2++) {
                        float* c = acc[t][g * 2 + j2];
                        mma16816(c, ah[t], bh[j2], bh[j2 + 2]);
                        mma16816(c, ah[t], bl[j2], bl[j2 + 2]);
                        mma16816(c, al[t], bh[j2], bh[j2 + 2]);
                    }
                }
            }
        }
        if (++sidx >= NSTAGE) sidx = 0;
    }

    // Epilogue: direct fp32 STG (float2 sector-coalesced)
    #pragma unroll
    for (int t = 0; t < 2; t++) {
        int mr = m0 + wr * 32 + t * 16 + (lid >> 2);
        #pragma unroll
        for (int j = 0; j < 8; j++) {
            int col = n0 + wc * 64 + j * 8 + (lid & 3) * 2;
            *reinterpret_cast<float2*>(out + (size_t)mr * HOUT + col) =
                make_float2(acc[t][j][0], acc[t][j][1]);
            *reinterpret_cast<float2*>(out + (size_t)(mr + 8) * HOUT + col) =
                make_float2(acc[t][j][2], acc[t][j][3]);
        }
    }
}

// ================= launch =================
extern "C" void kernel_launch(void* const* d_in, const int* in_sizes, int n_in,
                              void* d_out, int out_size) {
    const float* x       = (const float*)d_in[0];
    const float* tkw     = (const float*)d_in[1];
    const float* W       = (const float*)d_in[2];
    const float* qa      = (const float*)d_in[3];
    const float* qb      = (const float*)d_in[4];
    const float* scaling = (const float*)d_in[5];
    float* out = (float*)d_out;

    lora_a_kernel<<<B_DIM / 64, 256>>>(x, tkw, qa);
    cvt_w_kernel<<<HOUT, 256>>>(W, qb, scaling);
    cvt_x_kernel<<<B_DIM, 256>>>(x);

    cudaFuncSetAttribute(fused_gemm_kernel,
                         cudaFuncAttributeMaxDynamicSharedMemorySize, SMEM_TOTAL);
    dim3 grid(HOUT / 128, B_DIM / 128);
    fused_gemm_kernel<<<grid, 256, SMEM_TOTAL>>>(out);
}

// round 6
// speedup vs baseline: 1.5093x; 1.5093x over previous
#include <cuda_runtime.h>
#include <cuda_bf16.h>
#include <cstdint>
#include <cstddef>

#define B_DIM 8192
#define HIN   4096
#define HOUT  4096
#define KE    4128          // 4096 + 32 LoRA cols = 129 chunks of K=32

// ---------------- device scratch (bf16 hi/lo planes, LoRA cols baked in) ----------------
__device__ __align__(16) __nv_bfloat16 g_xh[(size_t)B_DIM * KE];
__device__ __align__(16) __nv_bfloat16 g_xl[(size_t)B_DIM * KE];
__device__ __align__(16) __nv_bfloat16 g_wh[(size_t)HOUT * KE];
__device__ __align__(16) __nv_bfloat16 g_wl[(size_t)HOUT * KE];

// ---------------- helpers ----------------
__device__ __forceinline__ uint32_t smem_u32(const void* p) {
    uint32_t a;
    asm("{ .reg .u64 t; cvta.to.shared.u64 t, %1; cvt.u32.u64 %0, t; }" : "=r"(a) : "l"(p));
    return a;
}

__device__ __forceinline__ void split4(float4 f, uint2& hv, uint2& lv) {
    __nv_bfloat16 h0 = __float2bfloat16(f.x);
    __nv_bfloat16 h1 = __float2bfloat16(f.y);
    __nv_bfloat16 h2 = __float2bfloat16(f.z);
    __nv_bfloat16 h3 = __float2bfloat16(f.w);
    __nv_bfloat16 l0 = __float2bfloat16(f.x - __bfloat162float(h0));
    __nv_bfloat16 l1 = __float2bfloat16(f.y - __bfloat162float(h1));
    __nv_bfloat16 l2 = __float2bfloat16(f.z - __bfloat162float(h2));
    __nv_bfloat16 l3 = __float2bfloat16(f.w - __bfloat162float(h3));
    hv.x = (uint32_t)__bfloat16_as_ushort(h0) | ((uint32_t)__bfloat16_as_ushort(h1) << 16);
    hv.y = (uint32_t)__bfloat16_as_ushort(h2) | ((uint32_t)__bfloat16_as_ushort(h3) << 16);
    lv.x = (uint32_t)__bfloat16_as_ushort(l0) | ((uint32_t)__bfloat16_as_ushort(l1) << 16);
    lv.y = (uint32_t)__bfloat16_as_ushort(l2) | ((uint32_t)__bfloat16_as_ushort(l3) << 16);
}

__device__ __forceinline__ void cpa16(uint32_t dst, const void* src) {
    asm volatile("cp.async.cg.shared.global [%0], [%1], 16;" :: "r"(dst), "l"(src));
}

__device__ __forceinline__ void ldm4(uint32_t* r, uint32_t addr) {
    asm volatile("ldmatrix.sync.aligned.m8n8.x4.shared.b16 {%0,%1,%2,%3}, [%4];"
                 : "=r"(r[0]), "=r"(r[1]), "=r"(r[2]), "=r"(r[3]) : "r"(addr));
}

__device__ __forceinline__ void mma16816(float* c, const uint32_t* a, uint32_t b0, uint32_t b1) {
    asm volatile(
        "mma.sync.aligned.m16n8k16.row.col.f32.bf16.bf16.f32 "
        "{%0,%1,%2,%3}, {%4,%5,%6,%7}, {%8,%9}, {%0,%1,%2,%3};"
        : "+f"(c[0]), "+f"(c[1]), "+f"(c[2]), "+f"(c[3])
        : "r"(a[0]), "r"(a[1]), "r"(a[2]), "r"(a[3]), "r"(b0), "r"(b1));
}

// ====== Stage 1: LoRA-A — writes bf16 hi/lo directly into x-plane columns [4096,4128) ======
__global__ void __launch_bounds__(256) lora_a_kernel(
    const float* __restrict__ x, const float* __restrict__ tkw, const float* __restrict__ qa)
{
    __shared__ float xs[64][64];
    __shared__ float qs[64][33];
    const int tid  = threadIdx.x;
    const int lane = tid & 31, w = tid >> 5;
    const int b0   = blockIdx.x * 64;

    float acc[8] = {0.f, 0.f, 0.f, 0.f, 0.f, 0.f, 0.f, 0.f};

    for (int k0 = 0; k0 < HIN; k0 += 64) {
        __syncthreads();
        #pragma unroll
        for (int i = 0; i < 4; i++) {
            int v = tid + i * 256;
            int r = v >> 4, c = (v & 15) << 2;
            *reinterpret_cast<float4*>(&xs[r][c]) =
                *reinterpret_cast<const float4*>(x + (size_t)(b0 + r) * HIN + k0 + c);
        }
        #pragma unroll
        for (int i = 0; i < 2; i++) {
            int v = tid + i * 256;
            int kr = v >> 4, c = (v & 15) << 2;
            float4 f = *reinterpret_cast<const float4*>(qa + (size_t)kr * HIN + k0 + c);
            qs[c + 0][kr] = f.x; qs[c + 1][kr] = f.y;
            qs[c + 2][kr] = f.z; qs[c + 3][kr] = f.w;
        }
        __syncthreads();
        #pragma unroll
        for (int kk = 0; kk < 64; kk += 4) {
            float q0 = qs[kk][lane], q1 = qs[kk + 1][lane];
            float q2 = qs[kk + 2][lane], q3 = qs[kk + 3][lane];
            #pragma unroll
            for (int i = 0; i < 8; i++) {
                float4 xv = *reinterpret_cast<const float4*>(&xs[w * 8 + i][kk]);
                acc[i] += xv.x * q0 + xv.y * q1 + xv.z * q2 + xv.w * q3;
            }
        }
    }
    #pragma unroll
    for (int i = 0; i < 8; i++) {
        int b = b0 + w * 8 + i;
        float v = acc[i] * tkw[b * 4 + (lane >> 3)];
        __nv_bfloat16 h = __float2bfloat16(v);
        __nv_bfloat16 l = __float2bfloat16(v - __bfloat162float(h));
        g_xh[(size_t)b * KE + 4096 + lane] = h;
        g_xl[(size_t)b * KE + 4096 + lane] = l;
    }
}

// ================= Stage 2a: convert x -> bf16 hi/lo planes =================
__global__ void __launch_bounds__(256) cvt_x_kernel(const float* __restrict__ x)
{
    const int b = blockIdx.x, tid = threadIdx.x;
    const size_t rb = (size_t)b * KE;
    uint2 hv, lv;
    #pragma unroll
    for (int i = 0; i < 4; i++) {
        int c4 = (tid + i * 256) << 2;
        float4 f = *reinterpret_cast<const float4*>(x + (size_t)b * HIN + c4);
        split4(f, hv, lv);
        *reinterpret_cast<uint2*>(g_xh + rb + c4) = hv;
        *reinterpret_cast<uint2*>(g_xl + rb + c4) = lv;
    }
}

// ========== Stage 2b: convert W (+scaling*qb in cols [4096,4128)) -> bf16 hi/lo ==========
__global__ void __launch_bounds__(256) cvt_w_kernel(
    const float* __restrict__ W, const float* __restrict__ qb, const float* __restrict__ scaling)
{
    const int o = blockIdx.x, tid = threadIdx.x;
    const size_t rb = (size_t)o * KE;
    uint2 hv, lv;
    #pragma unroll
    for (int i = 0; i < 4; i++) {
        int c4 = (tid + i * 256) << 2;
        float4 f = *reinterpret_cast<const float4*>(W + (size_t)o * HIN + c4);
        split4(f, hv, lv);
        *reinterpret_cast<uint2*>(g_wh + rb + c4) = hv;
        *reinterpret_cast<uint2*>(g_wl + rb + c4) = lv;
    }
    if (tid < 8) {
        int c4 = 4096 + tid * 4;
        int kk = tid >> 1, rr = (tid & 1) * 4;       // kr = kk*8 + rr..rr+3
        const float* p = qb + ((size_t)kk * HOUT + o) * 8 + rr;
        float sc = scaling[o];
        float4 f = make_float4(p[0] * sc, p[1] * sc, p[2] * sc, p[3] * sc);
        split4(f, hv, lv);
        *reinterpret_cast<uint2*>(g_wh + rb + c4) = hv;
        *reinterpret_cast<uint2*>(g_wl + rb + c4) = lv;
    }
}

// ================= Stage 3: GEMM =================
// 512 threads (16 warps, 4x4), CTA tile M=128 x N=256, K=32 chunks.
// Smem row = 128B: [hi 64B | lo 64B]; 4-stage cp.async ring, wait_group 2.
#define A_OFF   0
#define W_OFF   16384
#define STAGE_B 49152
#define NSTAGE  4
#define SMEM_TOTAL (NSTAGE * STAGE_B)
#define NCHUNK  129

__device__ __forceinline__ void issue_stage(uint32_t st, int ch, int m0, int n0, int tid)
{
    const int r8 = tid >> 3, sg = tid & 7;           // row group, 16B segment
    const int plane = sg >> 2;                       // 0=hi, 1=lo
    const __nv_bfloat16* xp = plane ? g_xl : g_xh;
    const __nv_bfloat16* wp = plane ? g_wl : g_wh;
    const size_t kofs = (size_t)ch * 32 + (sg & 3) * 8;
    const uint32_t sgb = (uint32_t)sg * 16u;
    #pragma unroll
    for (int j = 0; j < 2; j++) {                    // A: 128 rows
        int row = r8 + 64 * j;
        uint32_t d = (uint32_t)row * 128u + (sgb ^ ((uint32_t)(row & 7) << 4));
        cpa16(st + A_OFF + d, xp + (size_t)(m0 + row) * KE + kofs);
    }
    #pragma unroll
    for (int j = 0; j < 4; j++) {                    // W: 256 rows
        int row = r8 + 64 * j;
        uint32_t d = (uint32_t)row * 128u + (sgb ^ ((uint32_t)(row & 7) << 4));
        cpa16(st + W_OFF + d, wp + (size_t)(n0 + row) * KE + kofs);
    }
    asm volatile("cp.async.commit_group;" ::: "memory");
}

__global__ void __launch_bounds__(512, 1) fused_gemm_kernel(float* __restrict__ out)
{
    extern __shared__ char smem[];
    const int tid = threadIdx.x;
    const int wid = tid >> 5, lid = tid & 31;
    const int wr = wid >> 2, wc = wid & 3;           // 4x4 warp grid
    const int n0 = blockIdx.x * 256;
    const int m0 = blockIdx.y * 128;
    const uint32_t sbase = smem_u32(smem);
    const int lr = lid & 15;
    const uint32_t lhb = (uint32_t)(lid >> 4) * 16u;

    float acc[2][8][4];
    #pragma unroll
    for (int t = 0; t < 2; t++)
        #pragma unroll
        for (int j = 0; j < 8; j++)
            #pragma unroll
            for (int e = 0; e < 4; e++) acc[t][j][e] = 0.f;

    issue_stage(sbase + 0 * STAGE_B, 0, m0, n0, tid);
    issue_stage(sbase + 1 * STAGE_B, 1, m0, n0, tid);
    issue_stage(sbase + 2 * STAGE_B, 2, m0, n0, tid);

    int sidx = 0;
    for (int ch = 0; ch < NCHUNK; ch++) {
        const uint32_t st = sbase + sidx * STAGE_B;

        asm volatile("cp.async.wait_group 2;" ::: "memory");
        __syncthreads();
        if (ch + 3 < NCHUNK) {
            int ps = sidx + 3; if (ps >= NSTAGE) ps -= NSTAGE;
            issue_stage(sbase + ps * STAGE_B, ch + 3, m0, n0, tid);
        } else {
            asm volatile("cp.async.commit_group;" ::: "memory");  // keep group count in step
        }

        #pragma unroll
        for (int ks = 0; ks < 2; ks++) {
            const uint32_t chb = (uint32_t)ks * 32u + lhb;
            uint32_t ah[2][4], al[2][4];
            #pragma unroll
            for (int t = 0; t < 2; t++) {
                uint32_t row = (uint32_t)(wr * 32 + t * 16 + lr);
                uint32_t rb = row * 128u, rx = (row & 7u) << 4;
                ldm4(ah[t], st + A_OFF + rb + (chb ^ rx));
                ldm4(al[t], st + A_OFF + rb + ((chb + 64u) ^ rx));
            }
            #pragma unroll
            for (int g = 0; g < 4; g++) {
                uint32_t row = (uint32_t)(wc * 64 + g * 16 + lr);
                uint32_t rb = row * 128u, rx = (row & 7u) << 4;
                uint32_t bh[4], bl[4];
                ldm4(bh, st + W_OFF + rb + (chb ^ rx));
                ldm4(bl, st + W_OFF + rb + ((chb + 64u) ^ rx));
                #pragma unroll
                for (int t = 0; t < 2; t++) {
                    #pragma unroll
                    for (int j2 = 0; j2 < 2; j2++) {
                        float* c = acc[t][g * 2 + j2];
                        mma16816(c, ah[t], bh[j2], bh[j2 + 2]);
                        mma16816(c, ah[t], bl[j2], bl[j2 + 2]);
                        mma16816(c, al[t], bh[j2], bh[j2 + 2]);
                    }
                }
            }
        }
        if (++sidx >= NSTAGE) sidx = 0;
    }

    // Epilogue: direct fp32 STG (float2 sector-coalesced)
    #pragma unroll
    for (int t = 0; t < 2; t++) {
        int mr = m0 + wr * 32 + t * 16 + (lid >> 2);
        #pragma unroll
        for (int j = 0; j < 8; j++) {
            int col = n0 + wc * 64 + j * 8 + (lid & 3) * 2;
            *reinterpret_cast<float2*>(out + (size_t)mr * HOUT + col) =
                make_float2(acc[t][j][0], acc[t][j][1]);
            *reinterpret_cast<float2*>(out + (size_t)(mr + 8) * HOUT + col) =
                make_float2(acc[t][j][2], acc[t][j][3]);
        }
    }
}

// ================= launch =================
extern "C" void kernel_launch(void* const* d_in, const int* in_sizes, int n_in,
                              void* d_out, int out_size) {
    const float* x       = (const float*)d_in[0];
    const float* tkw     = (const float*)d_in[1];
    const float* W       = (const float*)d_in[2];
    const float* qa      = (const float*)d_in[3];
    const float* qb      = (const float*)d_in[4];
    const float* scaling = (const float*)d_in[5];
    float* out = (float*)d_out;

    lora_a_kernel<<<B_DIM / 64, 256>>>(x, tkw, qa);
    cvt_w_kernel<<<HOUT, 256>>>(W, qb, scaling);
    cvt_x_kernel<<<B_DIM, 256>>>(x);

    cudaFuncSetAttribute(fused_gemm_kernel,
                         cudaFuncAttributeMaxDynamicSharedMemorySize, SMEM_TOTAL);
    dim3 grid(HOUT / 256, B_DIM / 128);
    fused_gemm_kernel<<<grid, 512, SMEM_TOTAL>>>(out);
}

// round 7
// speedup vs baseline: 3.7116x; 2.4592x over previous
#include <cuda_runtime.h>
#include <cuda_fp16.h>
#include <cstdint>
#include <cstddef>

#define B_DIM 8192
#define HIN   4096
#define HOUT  4096
#define KE    4160          // 4096 + 32 LoRA + 32 zero pad = 65 chunks of K=64

// ---------------- device scratch: single fp16 plane per operand ----------------
__device__ __align__(16) __half g_xp[(size_t)B_DIM * KE];
__device__ __align__(16) __half g_wp[(size_t)HOUT * KE];

// ---------------- helpers ----------------
__device__ __forceinline__ uint32_t smem_u32(const void* p) {
    uint32_t a;
    asm("{ .reg .u64 t; cvta.to.shared.u64 t, %1; cvt.u32.u64 %0, t; }" : "=r"(a) : "l"(p));
    return a;
}

__device__ __forceinline__ uint2 pack4h(float4 f) {
    __half2 a = __floats2half2_rn(f.x, f.y);
    __half2 b = __floats2half2_rn(f.z, f.w);
    uint2 r;
    r.x = *reinterpret_cast<uint32_t*>(&a);
    r.y = *reinterpret_cast<uint32_t*>(&b);
    return r;
}

__device__ __forceinline__ void cpa16(uint32_t dst, const void* src) {
    asm volatile("cp.async.cg.shared.global [%0], [%1], 16;" :: "r"(dst), "l"(src));
}

__device__ __forceinline__ void ldm4(uint32_t* r, uint32_t addr) {
    asm volatile("ldmatrix.sync.aligned.m8n8.x4.shared.b16 {%0,%1,%2,%3}, [%4];"
                 : "=r"(r[0]), "=r"(r[1]), "=r"(r[2]), "=r"(r[3]) : "r"(addr));
}

__device__ __forceinline__ void mma16816(float* c, const uint32_t* a, uint32_t b0, uint32_t b1) {
    asm volatile(
        "mma.sync.aligned.m16n8k16.row.col.f32.f16.f16.f32 "
        "{%0,%1,%2,%3}, {%4,%5,%6,%7}, {%8,%9}, {%0,%1,%2,%3};"
        : "+f"(c[0]), "+f"(c[1]), "+f"(c[2]), "+f"(c[3])
        : "r"(a[0]), "r"(a[1]), "r"(a[2]), "r"(a[3]), "r"(b0), "r"(b1));
}

// ====== Stage 1: LoRA-A — writes fp16 aw directly into x-plane columns [4096,4128) ======
__global__ void __launch_bounds__(256) lora_a_kernel(
    const float* __restrict__ x, const float* __restrict__ tkw, const float* __restrict__ qa)
{
    __shared__ float xs[64][64];
    __shared__ float qs[64][33];
    const int tid  = threadIdx.x;
    const int lane = tid & 31, w = tid >> 5;
    const int b0   = blockIdx.x * 64;

    float acc[8] = {0.f, 0.f, 0.f, 0.f, 0.f, 0.f, 0.f, 0.f};

    for (int k0 = 0; k0 < HIN; k0 += 64) {
        __syncthreads();
        #pragma unroll
        for (int i = 0; i < 4; i++) {
            int v = tid + i * 256;
            int r = v >> 4, c = (v & 15) << 2;
            *reinterpret_cast<float4*>(&xs[r][c]) =
                *reinterpret_cast<const float4*>(x + (size_t)(b0 + r) * HIN + k0 + c);
        }
        #pragma unroll
        for (int i = 0; i < 2; i++) {
            int v = tid + i * 256;
            int kr = v >> 4, c = (v & 15) << 2;
            float4 f = *reinterpret_cast<const float4*>(qa + (size_t)kr * HIN + k0 + c);
            qs[c + 0][kr] = f.x; qs[c + 1][kr] = f.y;
            qs[c + 2][kr] = f.z; qs[c + 3][kr] = f.w;
        }
        __syncthreads();
        #pragma unroll
        for (int kk = 0; kk < 64; kk += 4) {
            float q0 = qs[kk][lane], q1 = qs[kk + 1][lane];
            float q2 = qs[kk + 2][lane], q3 = qs[kk + 3][lane];
            #pragma unroll
            for (int i = 0; i < 8; i++) {
                float4 xv = *reinterpret_cast<const float4*>(&xs[w * 8 + i][kk]);
                acc[i] += xv.x * q0 + xv.y * q1 + xv.z * q2 + xv.w * q3;
            }
        }
    }
    #pragma unroll
    for (int i = 0; i < 8; i++) {
        int b = b0 + w * 8 + i;
        float v = acc[i] * tkw[b * 4 + (lane >> 3)];
        g_xp[(size_t)b * KE + 4096 + lane] = __float2half(v);
    }
}

// ================= Stage 2a: convert x -> fp16 plane (+pad zeros) =================
__global__ void __launch_bounds__(256) cvt_x_kernel(const float* __restrict__ x)
{
    const int b = blockIdx.x, tid = threadIdx.x;
    const size_t rb = (size_t)b * KE;
    #pragma unroll
    for (int i = 0; i < 4; i++) {
        int c4 = (tid + i * 256) << 2;
        float4 f = *reinterpret_cast<const float4*>(x + (size_t)b * HIN + c4);
        *reinterpret_cast<uint2*>(g_xp + rb + c4) = pack4h(f);
    }
    if (tid < 4)    // zero pad [4128, 4160)
        *reinterpret_cast<uint2*>(g_xp + rb + 4128 + tid * 8) = make_uint2(0u, 0u);
}

// ====== Stage 2b: convert W -> fp16 plane (+scaling*qb cols [4096,4128), +pad) ======
__global__ void __launch_bounds__(256) cvt_w_kernel(
    const float* __restrict__ W, const float* __restrict__ qb, const float* __restrict__ scaling)
{
    const int o = blockIdx.x, tid = threadIdx.x;
    const size_t rb = (size_t)o * KE;
    #pragma unroll
    for (int i = 0; i < 4; i++) {
        int c4 = (tid + i * 256) << 2;
        float4 f = *reinterpret_cast<const float4*>(W + (size_t)o * HIN + c4);
        *reinterpret_cast<uint2*>(g_wp + rb + c4) = pack4h(f);
    }
    if (tid < 8) {
        int c4 = 4096 + tid * 4;
        int kk = tid >> 1, rr = (tid & 1) * 4;       // kr = kk*8 + rr..rr+3
        const float* p = qb + ((size_t)kk * HOUT + o) * 8 + rr;
        float sc = scaling[o];
        float4 f = make_float4(p[0] * sc, p[1] * sc, p[2] * sc, p[3] * sc);
        *reinterpret_cast<uint2*>(g_wp + rb + c4) = pack4h(f);
    } else if (tid < 12) {  // zero pad [4128, 4160)
        *reinterpret_cast<uint2*>(g_wp + rb + 4128 + (tid - 8) * 8) = make_uint2(0u, 0u);
    }
}

// ================= Stage 3: GEMM (single-pass fp16) =================
// 512 threads (16 warps, 4x4), CTA tile M=128 x N=256, K=64 chunks.
// Smem row = 128B = 64 fp16 (one chunk row); 3-stage cp.async ring, wait_group 1.
#define A_OFF   0
#define W_OFF   16384
#define STAGE_B 49152
#define NSTAGE  3
#define SMEM_TOTAL (NSTAGE * STAGE_B)
#define NCHUNK  65

__device__ __forceinline__ void issue_stage(uint32_t st, int ch, int m0, int n0, int tid)
{
    const int r8 = tid >> 3, sg = tid & 7;           // row group, 16B segment
    const size_t kofs = (size_t)ch * 64 + sg * 8;
    const uint32_t sgb = (uint32_t)sg * 16u;
    #pragma unroll
    for (int j = 0; j < 2; j++) {                    // A: 128 rows
        int row = r8 + 64 * j;
        uint32_t d = (uint32_t)row * 128u + (sgb ^ ((uint32_t)(row & 7) << 4));
        cpa16(st + A_OFF + d, g_xp + (size_t)(m0 + row) * KE + kofs);
    }
    #pragma unroll
    for (int j = 0; j < 4; j++) {                    // W: 256 rows
        int row = r8 + 64 * j;
        uint32_t d = (uint32_t)row * 128u + (sgb ^ ((uint32_t)(row & 7) << 4));
        cpa16(st + W_OFF + d, g_wp + (size_t)(n0 + row) * KE + kofs);
    }
    asm volatile("cp.async.commit_group;" ::: "memory");
}

__global__ void __launch_bounds__(512, 1) fused_gemm_kernel(float* __restrict__ out)
{
    extern __shared__ char smem[];
    const int tid = threadIdx.x;
    const int wid = tid >> 5, lid = tid & 31;
    const int wr = wid >> 2, wc = wid & 3;           // 4x4 warp grid
    const int n0 = blockIdx.x * 256;
    const int m0 = blockIdx.y * 128;
    const uint32_t sbase = smem_u32(smem);
    const int lr = lid & 15;
    const uint32_t lhb = (uint32_t)(lid >> 4) * 16u;

    float acc[2][8][4];
    #pragma unroll
    for (int t = 0; t < 2; t++)
        #pragma unroll
        for (int j = 0; j < 8; j++)
            #pragma unroll
            for (int e = 0; e < 4; e++) acc[t][j][e] = 0.f;

    issue_stage(sbase + 0 * STAGE_B, 0, m0, n0, tid);
    issue_stage(sbase + 1 * STAGE_B, 1, m0, n0, tid);

    int sidx = 0;
    for (int ch = 0; ch < NCHUNK; ch++) {
        const uint32_t st = sbase + sidx * STAGE_B;

        asm volatile("cp.async.wait_group 1;" ::: "memory");
        __syncthreads();
        if (ch + 2 < NCHUNK) {
            int ps = sidx + 2; if (ps >= NSTAGE) ps -= NSTAGE;
            issue_stage(sbase + ps * STAGE_B, ch + 2, m0, n0, tid);
        } else {
            asm volatile("cp.async.commit_group;" ::: "memory");  // keep group count in step
        }

        #pragma unroll
        for (int ks = 0; ks < 4; ks++) {             // 4 k16 steps per K=64 chunk
            const uint32_t chb = (uint32_t)ks * 32u + lhb;
            uint32_t ah[2][4];
            #pragma unroll
            for (int t = 0; t < 2; t++) {
                uint32_t row = (uint32_t)(wr * 32 + t * 16 + lr);
                uint32_t d = row * 128u + (chb ^ ((row & 7u) << 4));
                ldm4(ah[t], st + A_OFF + d);
            }
            #pragma unroll
            for (int g = 0; g < 4; g++) {
                uint32_t row = (uint32_t)(wc * 64 + g * 16 + lr);
                uint32_t d = row * 128u + (chb ^ ((row & 7u) << 4));
                uint32_t bh[4];
                ldm4(bh, st + W_OFF + d);
                #pragma unroll
                for (int t = 0; t < 2; t++) {
                    #pragma unroll
                    for (int j2 = 0; j2 < 2; j2++)
                        mma16816(acc[t][g * 2 + j2], ah[t], bh[j2], bh[j2 + 2]);
                }
            }
        }
        if (++sidx >= NSTAGE) sidx = 0;
    }

    // Epilogue: direct fp32 STG (float2 sector-coalesced)
    #pragma unroll
    for (int t = 0; t < 2; t++) {
        int mr = m0 + wr * 32 + t * 16 + (lid >> 2);
        #pragma unroll
        for (int j = 0; j < 8; j++) {
            int col = n0 + wc * 64 + j * 8 + (lid & 3) * 2;
            *reinterpret_cast<float2*>(out + (size_t)mr * HOUT + col) =
                make_float2(acc[t][j][0], acc[t][j][1]);
            *reinterpret_cast<float2*>(out + (size_t)(mr + 8) * HOUT + col) =
                make_float2(acc[t][j][2], acc[t][j][3]);
        }
    }
}

// ================= launch =================
extern "C" void kernel_launch(void* const* d_in, const int* in_sizes, int n_in,
                              void* d_out, int out_size) {
    const float* x       = (const float*)d_in[0];
    const float* tkw     = (const float*)d_in[1];
    const float* W       = (const float*)d_in[2];
    const float* qa      = (const float*)d_in[3];
    const float* qb      = (const float*)d_in[4];
    const float* scaling = (const float*)d_in[5];
    float* out = (float*)d_out;

    lora_a_kernel<<<B_DIM / 64, 256>>>(x, tkw, qa);
    cvt_w_kernel<<<HOUT, 256>>>(W, qb, scaling);
    cvt_x_kernel<<<B_DIM, 256>>>(x);

    cudaFuncSetAttribute(fused_gemm_kernel,
                         cudaFuncAttributeMaxDynamicSharedMemorySize, SMEM_TOTAL);
    dim3 grid(HOUT / 256, B_DIM / 128);
    fused_gemm_kernel<<<grid, 512, SMEM_TOTAL>>>(out);
}

// round 8
// speedup vs baseline: 3.8355x; 1.0334x over previous
#include <cuda_runtime.h>
#include <cuda_fp16.h>
#include <cstdint>
#include <cstddef>

#define B_DIM 8192
#define HIN   4096
#define HOUT  4096
#define KE    4160          // 4096 + 32 LoRA + 32 zero pad = 65 chunks of K=64

// ---------------- device scratch: single fp16 plane per operand ----------------
__device__ __align__(16) __half g_xp[(size_t)B_DIM * KE];
__device__ __align__(16) __half g_wp[(size_t)HOUT * KE];

// ---------------- helpers ----------------
__device__ __forceinline__ uint32_t smem_u32(const void* p) {
    uint32_t a;
    asm("{ .reg .u64 t; cvta.to.shared.u64 t, %1; cvt.u32.u64 %0, t; }" : "=r"(a) : "l"(p));
    return a;
}

__device__ __forceinline__ uint2 pack4h(float4 f) {
    __half2 a = __floats2half2_rn(f.x, f.y);
    __half2 b = __floats2half2_rn(f.z, f.w);
    uint2 r;
    r.x = *reinterpret_cast<uint32_t*>(&a);
    r.y = *reinterpret_cast<uint32_t*>(&b);
    return r;
}

__device__ __forceinline__ void cpa16(uint32_t dst, const void* src) {
    asm volatile("cp.async.cg.shared.global [%0], [%1], 16;" :: "r"(dst), "l"(src));
}

__device__ __forceinline__ void ldm4(uint32_t* r, uint32_t addr) {
    asm volatile("ldmatrix.sync.aligned.m8n8.x4.shared.b16 {%0,%1,%2,%3}, [%4];"
                 : "=r"(r[0]), "=r"(r[1]), "=r"(r[2]), "=r"(r[3]) : "r"(addr));
}

__device__ __forceinline__ void mma16816(float* c, const uint32_t* a, uint32_t b0, uint32_t b1) {
    asm volatile(
        "mma.sync.aligned.m16n8k16.row.col.f32.f16.f16.f32 "
        "{%0,%1,%2,%3}, {%4,%5,%6,%7}, {%8,%9}, {%0,%1,%2,%3};"
        : "+f"(c[0]), "+f"(c[1]), "+f"(c[2]), "+f"(c[3])
        : "r"(a[0]), "r"(a[1]), "r"(a[2]), "r"(a[3]), "r"(b0), "r"(b1));
}

// ====== Stage 1: LoRA-A + x conversion fused ======
// Computes aw = (x @ qa^T)*tkw into x-plane cols [4096,4128), converts x tile
// (already staged in smem) into the fp16 plane, and zero-pads [4128,4160).
__global__ void __launch_bounds__(256) lora_a_kernel(
    const float* __restrict__ x, const float* __restrict__ tkw, const float* __restrict__ qa)
{
    __shared__ float xs[64][64];
    __shared__ float qs[64][33];
    const int tid  = threadIdx.x;
    const int lane = tid & 31, w = tid >> 5;
    const int b0   = blockIdx.x * 64;

    float acc[8] = {0.f, 0.f, 0.f, 0.f, 0.f, 0.f, 0.f, 0.f};

    for (int k0 = 0; k0 < HIN; k0 += 64) {
        __syncthreads();
        #pragma unroll
        for (int i = 0; i < 4; i++) {
            int v = tid + i * 256;
            int r = v >> 4, c = (v & 15) << 2;
            *reinterpret_cast<float4*>(&xs[r][c]) =
                *reinterpret_cast<const float4*>(x + (size_t)(b0 + r) * HIN + k0 + c);
        }
        #pragma unroll
        for (int i = 0; i < 2; i++) {
            int v = tid + i * 256;
            int kr = v >> 4, c = (v & 15) << 2;
            float4 f = *reinterpret_cast<const float4*>(qa + (size_t)kr * HIN + k0 + c);
            qs[c + 0][kr] = f.x; qs[c + 1][kr] = f.y;
            qs[c + 2][kr] = f.z; qs[c + 3][kr] = f.w;
        }
        __syncthreads();
        // fused x -> fp16 plane conversion (reads the staged tile from smem)
        #pragma unroll
        for (int i = 0; i < 4; i++) {
            int v = tid + i * 256;
            int r = v >> 4, c = (v & 15) << 2;
            float4 f = *reinterpret_cast<const float4*>(&xs[r][c]);
            *reinterpret_cast<uint2*>(g_xp + (size_t)(b0 + r) * KE + k0 + c) = pack4h(f);
        }
        #pragma unroll
        for (int kk = 0; kk < 64; kk += 4) {
            float q0 = qs[kk][lane], q1 = qs[kk + 1][lane];
            float q2 = qs[kk + 2][lane], q3 = qs[kk + 3][lane];
            #pragma unroll
            for (int i = 0; i < 8; i++) {
                float4 xv = *reinterpret_cast<const float4*>(&xs[w * 8 + i][kk]);
                acc[i] += xv.x * q0 + xv.y * q1 + xv.z * q2 + xv.w * q3;
            }
        }
    }
    #pragma unroll
    for (int i = 0; i < 8; i++) {
        int b = b0 + w * 8 + i;
        float v = acc[i] * tkw[b * 4 + (lane >> 3)];
        g_xp[(size_t)b * KE + 4096 + lane] = __float2half(v);
    }
    // zero pad cols [4128, 4160): 64 rows x 4 uint2 each
    {
        int r = tid >> 2, seg = tid & 3;
        *reinterpret_cast<uint2*>(g_xp + (size_t)(b0 + r) * KE + 4128 + seg * 8) =
            make_uint2(0u, 0u);
    }
}

// ====== Stage 2: convert W -> fp16 plane (+scaling*qb cols [4096,4128), +pad) ======
__global__ void __launch_bounds__(256) cvt_w_kernel(
    const float* __restrict__ W, const float* __restrict__ qb, const float* __restrict__ scaling)
{
    const int o = blockIdx.x, tid = threadIdx.x;
    const size_t rb = (size_t)o * KE;
    #pragma unroll
    for (int i = 0; i < 4; i++) {
        int c4 = (tid + i * 256) << 2;
        float4 f = *reinterpret_cast<const float4*>(W + (size_t)o * HIN + c4);
        *reinterpret_cast<uint2*>(g_wp + rb + c4) = pack4h(f);
    }
    if (tid < 8) {
        int c4 = 4096 + tid * 4;
        int kk = tid >> 1, rr = (tid & 1) * 4;       // kr = kk*8 + rr..rr+3
        const float* p = qb + ((size_t)kk * HOUT + o) * 8 + rr;
        float sc = scaling[o];
        float4 f = make_float4(p[0] * sc, p[1] * sc, p[2] * sc, p[3] * sc);
        *reinterpret_cast<uint2*>(g_wp + rb + c4) = pack4h(f);
    } else if (tid < 12) {  // zero pad [4128, 4160)
        *reinterpret_cast<uint2*>(g_wp + rb + 4128 + (tid - 8) * 8) = make_uint2(0u, 0u);
    }
}

// ================= Stage 3: GEMM (single-pass fp16, B-pipelined) =================
// 512 threads (16 warps, 4x4), CTA tile M=128 x N=256, K=64 chunks.
// Smem row = 128B = 64 fp16; 3-stage cp.async ring, wait_group 1.
#define A_OFF   0
#define W_OFF   16384
#define STAGE_B 49152
#define NSTAGE  3
#define SMEM_TOTAL (NSTAGE * STAGE_B)
#define NCHUNK  65

__device__ __forceinline__ void issue_stage(uint32_t st, int ch, int m0, int n0, int tid)
{
    const int r8 = tid >> 3, sg = tid & 7;           // row group, 16B segment
    const size_t kofs = (size_t)ch * 64 + sg * 8;
    const uint32_t sgb = (uint32_t)sg * 16u;
    #pragma unroll
    for (int j = 0; j < 2; j++) {                    // A: 128 rows
        int row = r8 + 64 * j;
        uint32_t d = (uint32_t)row * 128u + (sgb ^ ((uint32_t)(row & 7) << 4));
        cpa16(st + A_OFF + d, g_xp + (size_t)(m0 + row) * KE + kofs);
    }
    #pragma unroll
    for (int j = 0; j < 4; j++) {                    // W: 256 rows
        int row = r8 + 64 * j;
        uint32_t d = (uint32_t)row * 128u + (sgb ^ ((uint32_t)(row & 7) << 4));
        cpa16(st + W_OFF + d, g_wp + (size_t)(n0 + row) * KE + kofs);
    }
    asm volatile("cp.async.commit_group;" ::: "memory");
}

__global__ void __launch_bounds__(512, 1) fused_gemm_kernel(float* __restrict__ out)
{
    extern __shared__ char smem[];
    const int tid = threadIdx.x;
    const int wid = tid >> 5, lid = tid & 31;
    const int wr = wid >> 2, wc = wid & 3;           // 4x4 warp grid
    const int n0 = blockIdx.x * 256;
    const int m0 = blockIdx.y * 128;
    const uint32_t sbase = smem_u32(smem);
    const int lr = lid & 15;
    const uint32_t lhb = (uint32_t)(lid >> 4) * 16u;

    // loop-invariant row bases (swizzle XOR term applied per-ks)
    uint32_t abase[2], arx[2], bbase[4], brx[4];
    #pragma unroll
    for (int t = 0; t < 2; t++) {
        uint32_t row = (uint32_t)(wr * 32 + t * 16 + lr);
        abase[t] = row * 128u; arx[t] = (row & 7u) << 4;
    }
    #pragma unroll
    for (int g = 0; g < 4; g++) {
        uint32_t row = (uint32_t)(wc * 64 + g * 16 + lr);
        bbase[g] = row * 128u; brx[g] = (row & 7u) << 4;
    }

    float acc[2][8][4];
    #pragma unroll
    for (int t = 0; t < 2; t++)
        #pragma unroll
        for (int j = 0; j < 8; j++)
            #pragma unroll
            for (int e = 0; e < 4; e++) acc[t][j][e] = 0.f;

    issue_stage(sbase + 0 * STAGE_B, 0, m0, n0, tid);
    issue_stage(sbase + 1 * STAGE_B, 1, m0, n0, tid);

    int sidx = 0;
    for (int ch = 0; ch < NCHUNK; ch++) {
        const uint32_t st = sbase + sidx * STAGE_B;
        const uint32_t sa = st + A_OFF, sw = st + W_OFF;

        asm volatile("cp.async.wait_group 1;" ::: "memory");
        __syncthreads();
        if (ch + 2 < NCHUNK) {
            int ps = sidx + 2; if (ps >= NSTAGE) ps -= NSTAGE;
            issue_stage(sbase + ps * STAGE_B, ch + 2, m0, n0, tid);
        } else {
            asm volatile("cp.async.commit_group;" ::: "memory");  // keep group count in step
        }

        #pragma unroll
        for (int ks = 0; ks < 4; ks++) {             // 4 k16 steps per K=64 chunk
            const uint32_t chb = (uint32_t)ks * 32u + lhb;
            uint32_t ah[2][4];
            ldm4(ah[0], sa + abase[0] + (chb ^ arx[0]));
            ldm4(ah[1], sa + abase[1] + (chb ^ arx[1]));

            uint32_t bfrag[2][4];                    // double-buffered B fragments
            ldm4(bfrag[0], sw + bbase[0] + (chb ^ brx[0]));
            #pragma unroll
            for (int g = 0; g < 4; g++) {
                const int cur = g & 1;
                if (g < 3)
                    ldm4(bfrag[cur ^ 1], sw + bbase[g + 1] + (chb ^ brx[g + 1]));
                #pragma unroll
                for (int t = 0; t < 2; t++) {
                    #pragma unroll
                    for (int j2 = 0; j2 < 2; j2++)
                        mma16816(acc[t][g * 2 + j2], ah[t],
                                 bfrag[cur][j2], bfrag[cur][j2 + 2]);
                }
            }
        }
        if (++sidx >= NSTAGE) sidx = 0;
    }

    // Epilogue: direct fp32 STG (float2 sector-coalesced)
    #pragma unroll
    for (int t = 0; t < 2; t++) {
        int mr = m0 + wr * 32 + t * 16 + (lid >> 2);
        #pragma unroll
        for (int j = 0; j < 8; j++) {
            int col = n0 + wc * 64 + j * 8 + (lid & 3) * 2;
            *reinterpret_cast<float2*>(out + (size_t)mr * HOUT + col) =
                make_float2(acc[t][j][0], acc[t][j][1]);
            *reinterpret_cast<float2*>(out + (size_t)(mr + 8) * HOUT + col) =
                make_float2(acc[t][j][2], acc[t][j][3]);
        }
    }
}

// ================= launch =================
extern "C" void kernel_launch(void* const* d_in, const int* in_sizes, int n_in,
                              void* d_out, int out_size) {
    const float* x       = (const float*)d_in[0];
    const float* tkw     = (const float*)d_in[1];
    const float* W       = (const float*)d_in[2];
    const float* qa      = (const float*)d_in[3];
    const float* qb      = (const float*)d_in[4];
    const float* scaling = (const float*)d_in[5];
    float* out = (float*)d_out;

    lora_a_kernel<<<B_DIM / 64, 256>>>(x, tkw, qa);
    cvt_w_kernel<<<HOUT, 256>>>(W, qb, scaling);

    cudaFuncSetAttribute(fused_gemm_kernel,
                         cudaFuncAttributeMaxDynamicSharedMemorySize, SMEM_TOTAL);
    dim3 grid(HOUT / 256, B_DIM / 128);
    fused_gemm_kernel<<<grid, 512, SMEM_TOTAL>>>(out);
}